// round 3
// baseline (speedup 1.0000x reference)
#include <cuda_runtime.h>
#include <cfloat>
#include <cstdint>

// Problem constants
#define B_   16
#define T_   2048
#define D_   100
#define G_   2
#define Q_   4
#define K_   1024
#define DG_  50          // per-group dim == codebook dim
#define N_   (B_ * T_)   // 32768 tokens
#define RS   52          // padded row stride (floats) -> 208B, 16B aligned rows

// Output layout (tuple order, flattened)
#define QUANT_OFF  0
#define LOSS_OFF   (N_ * D_)          // 3276800
#define COMMIT_OFF (LOSS_OFF + N_)    // 3309568
#define RECON_OFF  (COMMIT_OFF + 1)   // 3309569

// Stage kernel geometry
#define STG_THREADS 64
#define STG_BLOCKS  (N_ / STG_THREADS)   // 512 blocks per group
#define TILE_K      128                  // codebook rows per smem tile

// Scratch (device globals; no runtime allocation allowed)
__device__ __align__(16) float g_r0[G_ * N_ * RS];   // immutable projected input
__device__ __align__(16) float g_r [G_ * N_ * RS];   // running residual
__device__ float g_cn[G_ * Q_ * K_];                 // codebook squared norms
__device__ float g_part[G_ * Q_ * STG_BLOCKS];       // per-block commit partials
__device__ float g_commit;                           // final commit scalar

// ---------------------------------------------------------------------------
// 1) project_in: r = x_g @ W_in[g] + b_in[g]; write to both r0 and r
// ---------------------------------------------------------------------------
__global__ void proj_in_kernel(const float* __restrict__ x,
                               const float* __restrict__ W_in,
                               const float* __restrict__ b_in) {
    int g = blockIdx.y;
    __shared__ float sW[DG_ * DG_];
    __shared__ float sb[DG_];
    for (int i = threadIdx.x; i < DG_ * DG_; i += blockDim.x)
        sW[i] = W_in[g * DG_ * DG_ + i];
    if (threadIdx.x < DG_) sb[threadIdx.x] = b_in[g * DG_ + threadIdx.x];
    __syncthreads();

    int n = blockIdx.x * blockDim.x + threadIdx.x;   // token id
    const float* xr = x + (size_t)n * D_ + g * DG_;
    float xv[DG_];
#pragma unroll
    for (int d = 0; d < DG_; d++) xv[d] = xr[d];

    float* o0 = g_r0 + (size_t)(g * N_ + n) * RS;
    float* o1 = g_r  + (size_t)(g * N_ + n) * RS;
    for (int c = 0; c < DG_; c++) {
        float a = sb[c];
#pragma unroll
        for (int d = 0; d < DG_; d++) a = fmaf(xv[d], sW[d * DG_ + c], a);
        o0[c] = a;
        o1[c] = a;
    }
}

// ---------------------------------------------------------------------------
// 2) codebook squared norms: ||cb||^2 for all G*Q*K rows
// ---------------------------------------------------------------------------
__global__ void cnorm_kernel(const float* __restrict__ cb) {
    int row = blockIdx.x * blockDim.x + threadIdx.x;
    if (row < G_ * Q_ * K_) {
        const float* p = cb + (size_t)row * DG_;
        float s = 0.f;
#pragma unroll
        for (int c = 0; c < DG_; c++) s = fmaf(p[c], p[c], s);
        g_cn[row] = s;
    }
}

// ---------------------------------------------------------------------------
// 3) one RVQ stage: argmin_k (||c_k||^2 - 2 r.c_k), commit partial, r -= qv
//    One token per thread; codebook tiled through smem; strict '<' keeps the
//    first index on ties (matches jnp.argmin).
// ---------------------------------------------------------------------------
__global__ void __launch_bounds__(STG_THREADS)
stage_kernel(const float* __restrict__ cb, int q) {
    int g = blockIdx.y;
    int n = blockIdx.x * STG_THREADS + threadIdx.x;

    __shared__ __align__(16) float scb[TILE_K * RS];
    __shared__ float sn[TILE_K];
    __shared__ float sred[STG_THREADS];

    float* rp = g_r + (size_t)(g * N_ + n) * RS;
    float r[DG_];
    {
        const float4* rp4 = (const float4*)rp;
#pragma unroll
        for (int i = 0; i < 12; i++) {
            float4 v = rp4[i];
            r[4*i] = v.x; r[4*i+1] = v.y; r[4*i+2] = v.z; r[4*i+3] = v.w;
        }
        r[48] = rp[48]; r[49] = rp[49];
    }

    const float* cbg = cb + (size_t)(g * Q_ + q) * K_ * DG_;
    const float* cng = g_cn + (g * Q_ + q) * K_;

    float best = FLT_MAX;
    int bestk = 0;

    for (int t0 = 0; t0 < K_; t0 += TILE_K) {
        __syncthreads();
        // cooperative coalesced load of TILE_K codebook rows into padded smem
        for (int i = threadIdx.x; i < TILE_K * DG_; i += STG_THREADS) {
            int k = i / DG_;
            int c = i - k * DG_;
            scb[k * RS + c] = cbg[(size_t)(t0 + k) * DG_ + c];
        }
        for (int i = threadIdx.x; i < TILE_K; i += STG_THREADS)
            sn[i] = cng[t0 + i];
        __syncthreads();

#pragma unroll 4
        for (int k = 0; k < TILE_K; k++) {
            const float4* row = (const float4*)(scb + k * RS);
            float acc0 = 0.f, acc1 = 0.f;
#pragma unroll
            for (int i = 0; i < 12; i += 2) {
                float4 v0 = row[i];
                float4 v1 = row[i + 1];
                acc0 = fmaf(r[4*i],   v0.x, acc0);
                acc0 = fmaf(r[4*i+1], v0.y, acc0);
                acc0 = fmaf(r[4*i+2], v0.z, acc0);
                acc0 = fmaf(r[4*i+3], v0.w, acc0);
                acc1 = fmaf(r[4*i+4], v1.x, acc1);
                acc1 = fmaf(r[4*i+5], v1.y, acc1);
                acc1 = fmaf(r[4*i+6], v1.z, acc1);
                acc1 = fmaf(r[4*i+7], v1.w, acc1);
            }
            acc0 = fmaf(r[48], scb[k * RS + 48], acc0);
            acc1 = fmaf(r[49], scb[k * RS + 49], acc1);
            float acc = acc0 + acc1;
            float d = fmaf(-2.f, acc, sn[k]);     // ||c||^2 - 2 r.c
            if (d < best) { best = d; bestk = t0 + k; }
        }
    }

    // gather chosen code, commit contribution (qv - r)^2, residual update
    const float* cv = cbg + (size_t)bestk * DG_;
    float cs = 0.f;
#pragma unroll
    for (int c = 0; c < DG_; c++) {
        float qv = cv[c];
        float df = qv - r[c];
        cs = fmaf(df, df, cs);
        r[c] = r[c] - qv;
    }
    {
        float4* wp4 = (float4*)rp;
#pragma unroll
        for (int i = 0; i < 12; i++) {
            float4 v;
            v.x = r[4*i]; v.y = r[4*i+1]; v.z = r[4*i+2]; v.w = r[4*i+3];
            wp4[i] = v;
        }
        rp[48] = r[48]; rp[49] = r[49];
    }

    // deterministic block reduction of commit partials
    sred[threadIdx.x] = cs;
    __syncthreads();
    for (int s = STG_THREADS / 2; s > 0; s >>= 1) {
        if (threadIdx.x < s) sred[threadIdx.x] += sred[threadIdx.x + s];
        __syncthreads();
    }
    if (threadIdx.x == 0)
        g_part[(g * Q_ + q) * STG_BLOCKS + blockIdx.x] = sred[0];
}

// ---------------------------------------------------------------------------
// 4) finalize commit scalar (deterministic fixed-order sums)
// ---------------------------------------------------------------------------
__global__ void finalize_kernel(float* __restrict__ out) {
    __shared__ float s[G_ * Q_];
    int t = threadIdx.x;
    if (t < G_ * Q_) {
        const float* p = g_part + t * STG_BLOCKS;
        float a = 0.f;
        for (int i = 0; i < STG_BLOCKS; i++) a += p[i];
        s[t] = a / ((float)N_ * (float)DG_);      // mean over (B,T,CD)
    }
    __syncthreads();
    if (t == 0) {
        float tot = 0.f;
        for (int i = 0; i < G_ * Q_; i++) tot += s[i];
        tot *= (1.f / (float)(G_ * Q_));          // mean over stacked commits
        g_commit = tot;
        out[COMMIT_OFF] = tot;
    }
}

// ---------------------------------------------------------------------------
// 5) output: qout = r0 - r_final; quantized = qout @ W_out + b_out (interleaved
//    by group); recon = mean((x - quantized)^2, -1); loss = recon + commit
// ---------------------------------------------------------------------------
__global__ void out_kernel(const float* __restrict__ x,
                           const float* __restrict__ W_out,
                           const float* __restrict__ b_out,
                           float* __restrict__ out) {
    __shared__ float sW[G_ * DG_ * DG_];   // 5000 floats
    __shared__ float sb[G_ * DG_];
    for (int i = threadIdx.x; i < G_ * DG_ * DG_; i += blockDim.x)
        sW[i] = W_out[i];
    if (threadIdx.x < G_ * DG_) sb[threadIdx.x] = b_out[threadIdx.x];
    __syncthreads();

    int n = blockIdx.x * blockDim.x + threadIdx.x;
    float commit = g_commit;
    const float* xr = x + (size_t)n * D_;
    float rs = 0.f;

    for (int g = 0; g < G_; g++) {
        const float* p0 = g_r0 + (size_t)(g * N_ + n) * RS;
        const float* p1 = g_r  + (size_t)(g * N_ + n) * RS;
        float qv[DG_];
#pragma unroll
        for (int c = 0; c < DG_; c++) qv[c] = p0[c] - p1[c];
        for (int d = 0; d < DG_; d++) {
            float a = sb[g * DG_ + d];
#pragma unroll
            for (int c = 0; c < DG_; c++)
                a = fmaf(qv[c], sW[g * DG_ * DG_ + c * DG_ + d], a);
            int e = g * DG_ + d;
            float df = xr[e] - a;
            rs = fmaf(df, df, rs);
            out[(size_t)n * D_ + e] = a;
        }
    }
    rs = rs / (float)D_;
    out[LOSS_OFF  + n] = rs + commit;
    out[RECON_OFF + n] = rs;
}

// ---------------------------------------------------------------------------
// launch
// ---------------------------------------------------------------------------
extern "C" void kernel_launch(void* const* d_in, const int* in_sizes, int n_in,
                              void* d_out, int out_size) {
    const float* x     = (const float*)d_in[0];
    const float* W_in  = (const float*)d_in[1];
    const float* b_in  = (const float*)d_in[2];
    const float* W_out = (const float*)d_in[3];
    const float* b_out = (const float*)d_in[4];
    const float* cb    = (const float*)d_in[5];
    float* out = (float*)d_out;

    proj_in_kernel<<<dim3(N_ / 256, G_), 256>>>(x, W_in, b_in);
    cnorm_kernel<<<(G_ * Q_ * K_ + 255) / 256, 256>>>(cb);
    for (int q = 0; q < Q_; q++)
        stage_kernel<<<dim3(STG_BLOCKS, G_), STG_THREADS>>>(cb, q);
    finalize_kernel<<<1, 32>>>(out);
    out_kernel<<<N_ / 256, 256>>>(x, W_out, b_out, out);
}

// round 7
// speedup vs baseline: 1.1873x; 1.1873x over previous
#include <cuda_runtime.h>
#include <cfloat>
#include <cstdint>

// Problem constants
#define B_   16
#define T_   2048
#define D_   100
#define G_   2
#define Q_   4
#define K_   1024
#define DG_  50
#define N_   (B_ * T_)          // 32768 tokens
#define RS   52                 // padded smem row stride (floats)

// Output layout (tuple order, flattened)
#define LOSS_OFF   (N_ * D_)
#define COMMIT_OFF (LOSS_OFF + N_)
#define RECON_OFF  (COMMIT_OFF + 1)

// Mega kernel geometry: 64 threads, 2 tokens/thread -> 128 tokens/block
#define MTHREADS 64
#define TOKB     128
#define MBLOCKS  (N_ / TOKB)    // 256 blocks per group
#define TILE_K   128

// Scratch (device globals)
__device__ float g_cn[G_ * Q_ * K_];          // codebook squared norms
__device__ float g_part[G_ * Q_ * MBLOCKS];   // commit partials
__device__ float g_rec[G_ * N_];              // per-group recon partials
__device__ float g_commit;

// ---------------------------------------------------------------------------
// codebook squared norms (accumulation order must stay fixed: c = 0..49)
// ---------------------------------------------------------------------------
__global__ void cnorm_kernel(const float* __restrict__ cb) {
    int row = blockIdx.x * blockDim.x + threadIdx.x;
    if (row < G_ * Q_ * K_) {
        const float* p = cb + (size_t)row * DG_;
        float s = 0.f;
#pragma unroll
        for (int c = 0; c < DG_; c++) s = fmaf(p[c], p[c], s);
        g_cn[row] = s;
    }
}

// ---------------------------------------------------------------------------
// mega kernel: proj_in + 4 RVQ stages (residuals in registers) + proj_out +
// recon partials + commit partials. 2 tokens per thread.
// The x slice is staged in the scb buffer (aliased) during the prologue only;
// the epilogue recon re-reads x from global. Static smem = 37,080 B.
// Distance formula/accumulation split is bitwise identical to the validated
// R3 kernel: a00 covers elems {0-3,8-11,...,48}, a01 covers {4-7,...,49},
// d = fmaf(-2, a00+a01, ||c||^2); strict '<' keeps first index on ties.
// ---------------------------------------------------------------------------
__global__ void __launch_bounds__(MTHREADS)
mega_kernel(const float* __restrict__ x,
            const float* __restrict__ W_in,
            const float* __restrict__ b_in,
            const float* __restrict__ W_out,
            const float* __restrict__ b_out,
            const float* __restrict__ cb,
            float* __restrict__ out) {
    const int g   = blockIdx.y;
    const int blk = blockIdx.x;
    const int tid = threadIdx.x;
    const int n0  = blk * TOKB + tid;
    const int n1  = n0 + MTHREADS;

    __shared__ __align__(16) float scb[TILE_K * RS];  // codebook tile / x staging
    __shared__ float sw[DG_ * DG_];                   // W_in, later W_out
    __shared__ float sb[DG_];                         // b_in, later b_out
    __shared__ float sred[MTHREADS];

    // ---- prologue: stage x slice (aliased into scb) + W_in; r0 -> registers ----
    float* sx = scb;                                  // 6400 floats <= 6656 capacity
    for (int i = tid; i < DG_ * DG_; i += MTHREADS) sw[i] = W_in[g * DG_ * DG_ + i];
    if (tid < DG_) sb[tid] = b_in[g * DG_ + tid];
    for (int i = tid; i < TOKB * DG_; i += MTHREADS) {
        int tok = i / DG_, d = i - tok * DG_;
        sx[i] = x[(size_t)(blk * TOKB + tok) * D_ + g * DG_ + d];
    }
    __syncthreads();

    float rA[DG_], rB[DG_];
#pragma unroll
    for (int c = 0; c < DG_; c++) {
        float aA = sb[c], aB = sb[c];
        for (int d = 0; d < DG_; d++) {
            float w = sw[d * DG_ + c];
            aA = fmaf(sx[tid * DG_ + d], w, aA);
            aB = fmaf(sx[(tid + MTHREADS) * DG_ + d], w, aB);
        }
        rA[c] = aA; rB[c] = aB;
    }

    // ---- 4 residual-VQ stages (scb now reused for codebook tiles) ----
    const float* cbg0 = cb + (size_t)g * Q_ * K_ * DG_;
    int idxA[Q_], idxB[Q_];

    for (int q = 0; q < Q_; q++) {
        const float* cbg = cbg0 + (size_t)q * K_ * DG_;
        const float* cng = g_cn + (g * Q_ + q) * K_;
        float bestA = FLT_MAX, bestB = FLT_MAX;
        int kA = 0, kB = 0;

        for (int t0 = 0; t0 < K_; t0 += TILE_K) {
            __syncthreads();
            for (int i = tid; i < TILE_K * DG_; i += MTHREADS) {
                int k = i / DG_, c = i - k * DG_;
                scb[k * RS + c] = cbg[(size_t)(t0 + k) * DG_ + c];
            }
            for (int k = tid; k < TILE_K; k += MTHREADS)
                scb[k * RS + DG_] = cng[t0 + k];
            __syncthreads();

#pragma unroll 2
            for (int k = 0; k < TILE_K; k++) {
                const float4* row = (const float4*)(scb + k * RS);
                float a00 = 0.f, a01 = 0.f, b00 = 0.f, b01 = 0.f;
#pragma unroll
                for (int i = 0; i < 12; i += 2) {
                    float4 v0 = row[i];
                    float4 v1 = row[i + 1];
                    a00 = fmaf(rA[4*i],   v0.x, a00);
                    a00 = fmaf(rA[4*i+1], v0.y, a00);
                    a00 = fmaf(rA[4*i+2], v0.z, a00);
                    a00 = fmaf(rA[4*i+3], v0.w, a00);
                    a01 = fmaf(rA[4*i+4], v1.x, a01);
                    a01 = fmaf(rA[4*i+5], v1.y, a01);
                    a01 = fmaf(rA[4*i+6], v1.z, a01);
                    a01 = fmaf(rA[4*i+7], v1.w, a01);
                    b00 = fmaf(rB[4*i],   v0.x, b00);
                    b00 = fmaf(rB[4*i+1], v0.y, b00);
                    b00 = fmaf(rB[4*i+2], v0.z, b00);
                    b00 = fmaf(rB[4*i+3], v0.w, b00);
                    b01 = fmaf(rB[4*i+4], v1.x, b01);
                    b01 = fmaf(rB[4*i+5], v1.y, b01);
                    b01 = fmaf(rB[4*i+6], v1.z, b01);
                    b01 = fmaf(rB[4*i+7], v1.w, b01);
                }
                float4 tl = row[12];          // c48, c49, ||c||^2, pad
                a00 = fmaf(rA[48], tl.x, a00);
                a01 = fmaf(rA[49], tl.y, a01);
                b00 = fmaf(rB[48], tl.x, b00);
                b01 = fmaf(rB[49], tl.y, b01);
                float dA = fmaf(-2.f, a00 + a01, tl.z);
                float dB = fmaf(-2.f, b00 + b01, tl.z);
                if (dA < bestA) { bestA = dA; kA = t0 + k; }
                if (dB < bestB) { bestB = dB; kB = t0 + k; }
            }
        }
        idxA[q] = kA; idxB[q] = kB;

        // gather chosen codes, commit contributions, residual update
        const float* cvA = cbg + (size_t)kA * DG_;
        const float* cvB = cbg + (size_t)kB * DG_;
        float csA = 0.f, csB = 0.f;
#pragma unroll
        for (int c = 0; c < DG_; c++) {
            float qa = cvA[c], qb = cvB[c];
            float da = qa - rA[c], db = qb - rB[c];
            csA = fmaf(da, da, csA);
            csB = fmaf(db, db, csB);
            rA[c] -= qa; rB[c] -= qb;
        }

        // deterministic block reduction of commit partials
        sred[tid] = csA + csB;
        __syncthreads();
        for (int s = MTHREADS / 2; s > 0; s >>= 1) {
            if (tid < s) sred[tid] += sred[tid + s];
            __syncthreads();
        }
        if (tid == 0) g_part[(g * Q_ + q) * MBLOCKS + blk] = sred[0];
    }

    // ---- qout = sum of chosen codes (reuse rA/rB) ----
#pragma unroll
    for (int c = 0; c < DG_; c++) { rA[c] = 0.f; rB[c] = 0.f; }
    for (int q = 0; q < Q_; q++) {
        const float* cA = cbg0 + (size_t)(q * K_ + idxA[q]) * DG_;
        const float* cB = cbg0 + (size_t)(q * K_ + idxB[q]) * DG_;
#pragma unroll
        for (int c = 0; c < DG_; c++) { rA[c] += cA[c]; rB[c] += cB[c]; }
    }

    // ---- proj_out + recon partials (x re-read from global) ----
    __syncthreads();
    for (int i = tid; i < DG_ * DG_; i += MTHREADS) sw[i] = W_out[g * DG_ * DG_ + i];
    if (tid < DG_) sb[tid] = b_out[g * DG_ + tid];
    __syncthreads();

    const float* xA = x + (size_t)n0 * D_ + g * DG_;
    const float* xB = x + (size_t)n1 * D_ + g * DG_;
    float rsA = 0.f, rsB = 0.f;
    for (int d = 0; d < DG_; d++) {
        float aA = sb[d], aB = sb[d];
#pragma unroll
        for (int c = 0; c < DG_; c++) {
            float w = sw[c * DG_ + d];
            aA = fmaf(rA[c], w, aA);
            aB = fmaf(rB[c], w, aB);
        }
        out[(size_t)n0 * D_ + g * DG_ + d] = aA;
        out[(size_t)n1 * D_ + g * DG_ + d] = aB;
        float eA = xA[d] - aA;
        float eB = xB[d] - aB;
        rsA = fmaf(eA, eA, rsA);
        rsB = fmaf(eB, eB, rsB);
    }
    g_rec[g * N_ + n0] = rsA;
    g_rec[g * N_ + n1] = rsB;
}

// ---------------------------------------------------------------------------
// commit scalar (deterministic fixed-order sums)
// ---------------------------------------------------------------------------
__global__ void finalize_kernel(float* __restrict__ out) {
    __shared__ float s[G_ * Q_];
    int t = threadIdx.x;
    if (t < G_ * Q_) {
        const float* p = g_part + t * MBLOCKS;
        float a = 0.f;
        for (int i = 0; i < MBLOCKS; i++) a += p[i];
        s[t] = a / ((float)N_ * (float)DG_);
    }
    __syncthreads();
    if (t == 0) {
        float tot = 0.f;
        for (int i = 0; i < G_ * Q_; i++) tot += s[i];
        tot *= (1.f / (float)(G_ * Q_));
        g_commit = tot;
        out[COMMIT_OFF] = tot;
    }
}

// ---------------------------------------------------------------------------
// loss / recon finalize
// ---------------------------------------------------------------------------
__global__ void loss_kernel(float* __restrict__ out) {
    int n = blockIdx.x * blockDim.x + threadIdx.x;
    float rs = (g_rec[n] + g_rec[N_ + n]) * (1.f / (float)D_);
    out[LOSS_OFF  + n] = rs + g_commit;
    out[RECON_OFF + n] = rs;
}

// ---------------------------------------------------------------------------
// launch
// ---------------------------------------------------------------------------
extern "C" void kernel_launch(void* const* d_in, const int* in_sizes, int n_in,
                              void* d_out, int out_size) {
    const float* x     = (const float*)d_in[0];
    const float* W_in  = (const float*)d_in[1];
    const float* b_in  = (const float*)d_in[2];
    const float* W_out = (const float*)d_in[3];
    const float* b_out = (const float*)d_in[4];
    const float* cb    = (const float*)d_in[5];
    float* out = (float*)d_out;

    cnorm_kernel<<<(G_ * Q_ * K_ + 255) / 256, 256>>>(cb);
    mega_kernel<<<dim3(MBLOCKS, G_), MTHREADS>>>(x, W_in, b_in, W_out, b_out, cb, out);
    finalize_kernel<<<1, 32>>>(out);
    loss_kernel<<<N_ / 256, 256>>>(out);
}

// round 9
// speedup vs baseline: 1.2426x; 1.0466x over previous
#include <cuda_runtime.h>
#include <cfloat>
#include <cstdint>

// Problem constants
#define B_   16
#define T_   2048
#define D_   100
#define G_   2
#define Q_   4
#define K_   1024
#define DG_  50
#define N_   (B_ * T_)          // 32768 tokens
#define RS   52                 // padded smem row stride (floats)

// Output layout (tuple order, flattened)
#define LOSS_OFF   (N_ * D_)
#define COMMIT_OFF (LOSS_OFF + N_)
#define RECON_OFF  (COMMIT_OFF + 1)

// Mega kernel geometry: 64 threads, 2 tokens/thread -> 128 tokens/block
#define MTHREADS 64
#define TOKB     128
#define MBLOCKS  (N_ / TOKB)    // 256 blocks per group
#define TILE_K   128

// Scratch (device globals)
__device__ float g_cn[G_ * Q_ * K_];          // codebook squared norms
__device__ float g_part[G_ * Q_ * MBLOCKS];   // commit partials
__device__ float g_rec[G_ * N_];              // per-group recon partials
__device__ float g_commit;

// ---- packed f32x2 helpers (Blackwell FFMA2 path; PTX-only) ----
__device__ __forceinline__ unsigned long long pk2(float lo, float hi) {
    unsigned long long d;
    asm("mov.b64 %0, {%1, %2};" : "=l"(d) : "f"(lo), "f"(hi));
    return d;
}
__device__ __forceinline__ void upk2(float& lo, float& hi, unsigned long long v) {
    asm("mov.b64 {%0, %1}, %2;" : "=f"(lo), "=f"(hi) : "l"(v));
}
__device__ __forceinline__ void fma2(unsigned long long& d,
                                     unsigned long long a, unsigned long long b) {
    asm("fma.rn.f32x2 %0, %1, %2, %0;" : "+l"(d) : "l"(a), "l"(b));
}
__device__ __forceinline__ unsigned long long add2(unsigned long long a,
                                                   unsigned long long b) {
    unsigned long long d;
    asm("add.rn.f32x2 %0, %1, %2;" : "=l"(d) : "l"(a), "l"(b));
    return d;
}

// ---------------------------------------------------------------------------
// codebook squared norms (fixed accumulation order c = 0..49)
// ---------------------------------------------------------------------------
__global__ void cnorm_kernel(const float* __restrict__ cb) {
    int row = blockIdx.x * blockDim.x + threadIdx.x;
    if (row < G_ * Q_ * K_) {
        const float* p = cb + (size_t)row * DG_;
        float s = 0.f;
#pragma unroll
        for (int c = 0; c < DG_; c++) s = fmaf(p[c], p[c], s);
        g_cn[row] = s;
    }
}

// ---------------------------------------------------------------------------
// mega kernel: proj_in + 4 RVQ stages + proj_out + losses. 2 tokens/thread.
// Residuals are canonical as 25 packed f32x2 pairs per token; the distance
// dot uses fma.rn.f32x2 (FFMA2, 2 FMAs/instr) to halve fma-pipe occupancy.
// Each lane is an exact IEEE fp32 FMA; only summation association changes
// (validated harmless: R3/R7 already used non-reference association with
// zero selection flips). Strict '<' keeps first index on ties.
// ---------------------------------------------------------------------------
__global__ void __launch_bounds__(MTHREADS)
mega_kernel(const float* __restrict__ x,
            const float* __restrict__ W_in,
            const float* __restrict__ b_in,
            const float* __restrict__ W_out,
            const float* __restrict__ b_out,
            const float* __restrict__ cb,
            float* __restrict__ out) {
    const int g   = blockIdx.y;
    const int blk = blockIdx.x;
    const int tid = threadIdx.x;
    const int n0  = blk * TOKB + tid;
    const int n1  = n0 + MTHREADS;

    __shared__ __align__(16) float scb[TILE_K * RS];  // codebook tile / x staging
    __shared__ float sw[DG_ * DG_];                   // W_in, later W_out
    __shared__ float sb[DG_];                         // b_in, later b_out
    __shared__ float sred[MTHREADS];

    // ---- prologue: stage x slice (aliased into scb) + W_in; r0 -> packed regs ----
    float* sx = scb;                                  // 6400 floats <= 6656 capacity
    for (int i = tid; i < DG_ * DG_; i += MTHREADS) sw[i] = W_in[g * DG_ * DG_ + i];
    if (tid < DG_) sb[tid] = b_in[g * DG_ + tid];
    for (int i = tid; i < TOKB * DG_; i += MTHREADS) {
        int tok = i / DG_, d = i - tok * DG_;
        sx[i] = x[(size_t)(blk * TOKB + tok) * D_ + g * DG_ + d];
    }
    __syncthreads();

    unsigned long long pA[25], pB[25];                // packed residuals (canonical)
#pragma unroll
    for (int p = 0; p < 25; p++) {
        float aA0 = sb[2*p],     aB0 = sb[2*p];
        float aA1 = sb[2*p + 1], aB1 = sb[2*p + 1];
        for (int d = 0; d < DG_; d++) {
            float w0 = sw[d * DG_ + 2*p];
            float w1 = sw[d * DG_ + 2*p + 1];
            float xa = sx[tid * DG_ + d];
            float xb = sx[(tid + MTHREADS) * DG_ + d];
            aA0 = fmaf(xa, w0, aA0);
            aA1 = fmaf(xa, w1, aA1);
            aB0 = fmaf(xb, w0, aB0);
            aB1 = fmaf(xb, w1, aB1);
        }
        pA[p] = pk2(aA0, aA1);
        pB[p] = pk2(aB0, aB1);
    }

    // ---- 4 residual-VQ stages (scb reused for codebook tiles) ----
    const float* cbg0 = cb + (size_t)g * Q_ * K_ * DG_;
    int idxA[Q_], idxB[Q_];

    for (int q = 0; q < Q_; q++) {
        const float* cbg = cbg0 + (size_t)q * K_ * DG_;
        const float* cng = g_cn + (g * Q_ + q) * K_;
        float bestA = FLT_MAX, bestB = FLT_MAX;
        int kA = 0, kB = 0;

        for (int t0 = 0; t0 < K_; t0 += TILE_K) {
            __syncthreads();
            for (int i = tid; i < TILE_K * DG_; i += MTHREADS) {
                int k = i / DG_, c = i - k * DG_;
                scb[k * RS + c] = cbg[(size_t)(t0 + k) * DG_ + c];
            }
            for (int k = tid; k < TILE_K; k += MTHREADS)
                scb[k * RS + DG_] = cng[t0 + k];
            __syncthreads();

#pragma unroll 2
            for (int k = 0; k < TILE_K; k++) {
                const ulonglong2* row = (const ulonglong2*)(scb + k * RS);
                unsigned long long a0 = 0ull, a1 = 0ull, b0 = 0ull, b1 = 0ull;
#pragma unroll
                for (int i = 0; i < 12; i++) {
                    ulonglong2 v = row[i];           // 4 floats -> 2 packed pairs
                    fma2(a0, pA[2*i],     v.x);
                    fma2(a1, pA[2*i + 1], v.y);
                    fma2(b0, pB[2*i],     v.x);
                    fma2(b1, pB[2*i + 1], v.y);
                }
                ulonglong2 t = row[12];              // (c48,c49), (cnorm, pad)
                fma2(a0, pA[24], t.x);
                fma2(b0, pB[24], t.x);
                float cn = __uint_as_float((unsigned int)t.y);

                float lA, hA, lB, hB;
                upk2(lA, hA, add2(a0, a1));
                upk2(lB, hB, add2(b0, b1));
                float dA = fmaf(-2.f, lA + hA, cn);
                float dB = fmaf(-2.f, lB + hB, cn);
                if (dA < bestA) { bestA = dA; kA = t0 + k; }
                if (dB < bestB) { bestB = dB; kB = t0 + k; }
            }
        }
        idxA[q] = kA; idxB[q] = kB;

        // gather chosen codes, commit contributions (element order 0..49),
        // residual update; repack
        const float* cvA = cbg + (size_t)kA * DG_;
        const float* cvB = cbg + (size_t)kB * DG_;
        float csA = 0.f, csB = 0.f;
#pragma unroll
        for (int p = 0; p < 25; p++) {
            float lo, hi;
            upk2(lo, hi, pA[p]);
            float qa0 = cvA[2*p], qa1 = cvA[2*p + 1];
            float d0 = qa0 - lo, d1 = qa1 - hi;
            csA = fmaf(d0, d0, csA);
            csA = fmaf(d1, d1, csA);
            pA[p] = pk2(lo - qa0, hi - qa1);

            upk2(lo, hi, pB[p]);
            float qb0 = cvB[2*p], qb1 = cvB[2*p + 1];
            float e0 = qb0 - lo, e1 = qb1 - hi;
            csB = fmaf(e0, e0, csB);
            csB = fmaf(e1, e1, csB);
            pB[p] = pk2(lo - qb0, hi - qb1);
        }

        // deterministic block reduction of commit partials
        sred[tid] = csA + csB;
        __syncthreads();
        for (int s = MTHREADS / 2; s > 0; s >>= 1) {
            if (tid < s) sred[tid] += sred[tid + s];
            __syncthreads();
        }
        if (tid == 0) g_part[(g * Q_ + q) * MBLOCKS + blk] = sred[0];
    }

    // ---- qout = sum of chosen codes ----
    float qA[DG_], qB[DG_];
#pragma unroll
    for (int c = 0; c < DG_; c++) { qA[c] = 0.f; qB[c] = 0.f; }
    for (int q = 0; q < Q_; q++) {
        const float* cA = cbg0 + (size_t)(q * K_ + idxA[q]) * DG_;
        const float* cB = cbg0 + (size_t)(q * K_ + idxB[q]) * DG_;
#pragma unroll
        for (int c = 0; c < DG_; c++) { qA[c] += cA[c]; qB[c] += cB[c]; }
    }

    // ---- proj_out + recon partials (x re-read from global) ----
    __syncthreads();
    for (int i = tid; i < DG_ * DG_; i += MTHREADS) sw[i] = W_out[g * DG_ * DG_ + i];
    if (tid < DG_) sb[tid] = b_out[g * DG_ + tid];
    __syncthreads();

    const float* xA = x + (size_t)n0 * D_ + g * DG_;
    const float* xB = x + (size_t)n1 * D_ + g * DG_;
    float rsA = 0.f, rsB = 0.f;
    for (int d = 0; d < DG_; d++) {
        float aA = sb[d], aB = sb[d];
#pragma unroll
        for (int c = 0; c < DG_; c++) {
            float w = sw[c * DG_ + d];
            aA = fmaf(qA[c], w, aA);
            aB = fmaf(qB[c], w, aB);
        }
        out[(size_t)n0 * D_ + g * DG_ + d] = aA;
        out[(size_t)n1 * D_ + g * DG_ + d] = aB;
        float eA = xA[d] - aA;
        float eB = xB[d] - aB;
        rsA = fmaf(eA, eA, rsA);
        rsB = fmaf(eB, eB, rsB);
    }
    g_rec[g * N_ + n0] = rsA;
    g_rec[g * N_ + n1] = rsB;
}

// ---------------------------------------------------------------------------
// commit scalar (deterministic fixed-order sums)
// ---------------------------------------------------------------------------
__global__ void finalize_kernel(float* __restrict__ out) {
    __shared__ float s[G_ * Q_];
    int t = threadIdx.x;
    if (t < G_ * Q_) {
        const float* p = g_part + t * MBLOCKS;
        float a = 0.f;
        for (int i = 0; i < MBLOCKS; i++) a += p[i];
        s[t] = a / ((float)N_ * (float)DG_);
    }
    __syncthreads();
    if (t == 0) {
        float tot = 0.f;
        for (int i = 0; i < G_ * Q_; i++) tot += s[i];
        tot *= (1.f / (float)(G_ * Q_));
        g_commit = tot;
        out[COMMIT_OFF] = tot;
    }
}

// ---------------------------------------------------------------------------
// loss / recon finalize
// ---------------------------------------------------------------------------
__global__ void loss_kernel(float* __restrict__ out) {
    int n = blockIdx.x * blockDim.x + threadIdx.x;
    float rs = (g_rec[n] + g_rec[N_ + n]) * (1.f / (float)D_);
    out[LOSS_OFF  + n] = rs + g_commit;
    out[RECON_OFF + n] = rs;
}

// ---------------------------------------------------------------------------
// launch
// ---------------------------------------------------------------------------
extern "C" void kernel_launch(void* const* d_in, const int* in_sizes, int n_in,
                              void* d_out, int out_size) {
    const float* x     = (const float*)d_in[0];
    const float* W_in  = (const float*)d_in[1];
    const float* b_in  = (const float*)d_in[2];
    const float* W_out = (const float*)d_in[3];
    const float* b_out = (const float*)d_in[4];
    const float* cb    = (const float*)d_in[5];
    float* out = (float*)d_out;

    cnorm_kernel<<<(G_ * Q_ * K_ + 255) / 256, 256>>>(cb);
    mega_kernel<<<dim3(MBLOCKS, G_), MTHREADS>>>(x, W_in, b_in, W_out, b_out, cb, out);
    finalize_kernel<<<1, 32>>>(out);
    loss_kernel<<<N_ / 256, 256>>>(out);
}